// round 2
// baseline (speedup 1.0000x reference)
#include <cuda_runtime.h>
#include <math.h>

// Problem constants (fixed by the dataset)
#define VOCAB   32000
#define NBL     128        // B*L = 2*64
#define NK      64         // H (8 heads x 8 hph)

// Tiling for the main kernel
#define BM      32         // bl tile
#define BN      128        // vocab tile
#define TM      4
#define TN      4          // vocab elems per thread (2 packed pairs)
#define NTHREADS 256       // (BM/TM) * (BN/TN) = 8 * 32

typedef unsigned long long u64;

// ---------------------------------------------------------------------------
// Packed f32x2 helpers (Blackwell-only; not emitted by ptxas from plain C++)
// ---------------------------------------------------------------------------
__device__ __forceinline__ u64 pk(float x, float y) {
    u64 r; asm("mov.b64 %0, {%1, %2};" : "=l"(r) : "f"(x), "f"(y)); return r;
}
__device__ __forceinline__ void upk(u64 a, float& x, float& y) {
    asm("mov.b64 {%0, %1}, %2;" : "=f"(x), "=f"(y) : "l"(a));
}
__device__ __forceinline__ u64 mul2(u64 a, u64 b) {
    u64 r; asm("mul.rn.f32x2 %0, %1, %2;" : "=l"(r) : "l"(a), "l"(b)); return r;
}
__device__ __forceinline__ u64 fma2(u64 a, u64 b, u64 c) {
    u64 r; asm("fma.rn.f32x2 %0, %1, %2, %3;" : "=l"(r) : "l"(a), "l"(b), "l"(c)); return r;
}

// ---------------------------------------------------------------------------
// Device scratch (static globals — no runtime allocation)
// ---------------------------------------------------------------------------
__device__ float g_vem[NK * VOCAB];   // [k][v] = exp(-vp)
__device__ float g_vep[NK * VOCAB];   // [k][v] = exp(+vp)
__device__ u64   g_cp2[NK * NBL];     // [k][bl] = (cp, cp)
__device__ u64   g_ep2[NK * NBL];     // [k][bl] = (e^f, e^f)
__device__ u64   g_em2[NK * NBL];     // [k][bl] = (e^-f, e^-f)

// ---------------------------------------------------------------------------
// Single prep kernel: blocks 0..999 transpose+exp the vocab patterns
// (both global reads and writes coalesced via an smem tile); block 1000
// computes the per-(bl,k) duplicated coefficients.
// ---------------------------------------------------------------------------
__global__ void __launch_bounds__(NTHREADS)
prep_kernel(const float* __restrict__ freqs,
            const float* __restrict__ amps,
            const float* __restrict__ phases,
            const float* __restrict__ vp,
            const float* __restrict__ iph,
            const float* __restrict__ W) {
    if (blockIdx.x < 1000) {
        __shared__ float s[NK * 33];            // padded transpose tile (32 v x 64 k)
        const int vbase = blockIdx.x * 32;
        #pragma unroll
        for (int it = 0; it < 8; ++it) {        // coalesced read of vp[vbase..vbase+31][*]
            int j = threadIdx.x + it * NTHREADS;
            int v = j >> 6, k = j & 63;
            s[k * 33 + v] = vp[(long)(vbase + v) * NK + k];
        }
        __syncthreads();
        #pragma unroll
        for (int it = 0; it < 8; ++it) {        // coalesced write of [k][v] planes
            int j = threadIdx.x + it * NTHREADS;
            int k = j >> 5, v = j & 31;
            float x = s[k * 33 + v];
            long  o = (long)k * VOCAB + vbase + v;
            g_vem[o] = expf(-x);
            g_vep[o] = expf(x);
        }
    } else {
        #pragma unroll 4
        for (int it = 0; it < (NBL * NK) / NTHREADS; ++it) {
            int idx = threadIdx.x + it * NTHREADS;   // idx = bl*NK + k
            int bl = idx >> 6, k = idx & 63;
            float cp = amps[idx] * cosf(phases[idx] - iph[k]) * W[k >> 3];
            float f  = freqs[idx];
            float ep = expf(f), em = expf(-f);
            int o = k * NBL + bl;
            g_cp2[o] = pk(cp, cp);
            g_ep2[o] = pk(ep, ep);
            g_em2[o] = pk(em, em);
        }
    }
}

// ---------------------------------------------------------------------------
// Main kernel: out[bl][v] = sum_k cp * min(e^f * e^-vp, e^-f * e^vp) + bias
// Packed-f32x2 inner loop: 1.5 fma-pipe inst per output element per k.
// ---------------------------------------------------------------------------
__global__ void __launch_bounds__(NTHREADS, 1)
main_kernel(float* __restrict__ out, const float* __restrict__ bptr) {
    extern __shared__ char smem_raw[];
    float* s_em  = (float*)smem_raw;                               // [NK][BN]  32KB
    float* s_ep  = s_em + NK * BN;                                 // [NK][BN]  32KB
    u64*   s_cp2 = (u64*)(s_ep + NK * BN);                         // [NK][BM]  16KB
    u64*   s_ep2 = s_cp2 + NK * BM;                                // [NK][BM]  16KB
    u64*   s_em2 = s_ep2 + NK * BM;                                // [NK][BM]  16KB

    const int tid     = threadIdx.x;
    const int v_base  = blockIdx.x * BN;
    const int bl_base = blockIdx.y * BM;

    // Vocab tile: float4-vectorized coalesced loads into planar smem
    {
        float4* d_em = (float4*)s_em;
        float4* d_ep = (float4*)s_ep;
        #pragma unroll
        for (int it = 0; it < (NK * BN / 4) / NTHREADS; ++it) {    // 8 iters
            int idx4 = tid + it * NTHREADS;
            int k = idx4 >> 5, v4 = idx4 & 31;
            d_em[k * (BN / 4) + v4] = ((const float4*)(g_vem + (long)k * VOCAB + v_base))[v4];
            d_ep[k * (BN / 4) + v4] = ((const float4*)(g_vep + (long)k * VOCAB + v_base))[v4];
        }
    }
    // bl tile: duplicated-pair planes
    #pragma unroll
    for (int it = 0; it < (NK * BM) / NTHREADS; ++it) {            // 8 iters
        int idx = tid + it * NTHREADS;
        int k = idx >> 5, bl = idx & 31;
        int src = k * NBL + bl_base + bl;
        s_cp2[idx] = g_cp2[src];
        s_ep2[idx] = g_ep2[src];
        s_em2[idx] = g_em2[src];
    }
    __syncthreads();

    const int vcol  = tid & 31;
    const int blrow = tid >> 5;          // warp-uniform -> smem broadcast
    const int v0    = vcol * TN;
    const int bl0   = blrow * TM;

    u64 acc[TM][2];
    #pragma unroll
    for (int i = 0; i < TM; ++i) { acc[i][0] = 0ull; acc[i][1] = 0ull; }

    #pragma unroll 4
    for (int k = 0; k < NK; ++k) {
        const int bb = k * BM + bl0;
        u64 cp2[TM], ep2[TM], em2[TM];
        #pragma unroll
        for (int i = 0; i < TM; ++i) {
            cp2[i] = s_cp2[bb + i];
            ep2[i] = s_ep2[bb + i];
            em2[i] = s_em2[bb + i];
        }
        float4 vem = *(const float4*)&s_em[k * BN + v0];
        float4 vep = *(const float4*)&s_ep[k * BN + v0];
        u64 em01 = pk(vem.x, vem.y), em23 = pk(vem.z, vem.w);
        u64 ep01 = pk(vep.x, vep.y), ep23 = pk(vep.z, vep.w);

        #pragma unroll
        for (int i = 0; i < TM; ++i) {
            u64 t1 = mul2(ep2[i], em01);
            u64 t2 = mul2(em2[i], ep01);
            float a0, a1, b0, b1;
            upk(t1, a0, a1); upk(t2, b0, b1);
            acc[i][0] = fma2(cp2[i], pk(fminf(a0, b0), fminf(a1, b1)), acc[i][0]);

            u64 t3 = mul2(ep2[i], em23);
            u64 t4 = mul2(em2[i], ep23);
            float c0, c1, d0, d1;
            upk(t3, c0, c1); upk(t4, d0, d1);
            acc[i][1] = fma2(cp2[i], pk(fminf(c0, d0), fminf(c1, d1)), acc[i][1]);
        }
    }

    const float bias = bptr[0];
    #pragma unroll
    for (int i = 0; i < TM; ++i) {
        float r0, r1, r2, r3;
        upk(acc[i][0], r0, r1);
        upk(acc[i][1], r2, r3);
        float4 r = make_float4(r0 + bias, r1 + bias, r2 + bias, r3 + bias);
        *(float4*)&out[(size_t)(bl_base + bl0 + i) * VOCAB + v_base + v0] = r;
    }
}

// ---------------------------------------------------------------------------
extern "C" void kernel_launch(void* const* d_in, const int* in_sizes, int n_in,
                              void* d_out, int out_size) {
    const float* freqs  = (const float*)d_in[0];
    const float* amps   = (const float*)d_in[1];
    const float* phases = (const float*)d_in[2];
    const float* vp     = (const float*)d_in[3];
    const float* iph    = (const float*)d_in[4];
    const float* W      = (const float*)d_in[5];
    const float* b      = (const float*)d_in[6];
    float* out = (float*)d_out;

    prep_kernel<<<1001, NTHREADS>>>(freqs, amps, phases, vp, iph, W);

    const int smem_bytes = NK * BN * 2 * (int)sizeof(float)      // s_em + s_ep
                         + NK * BM * 3 * (int)sizeof(u64);       // 3 dup planes
    cudaFuncSetAttribute(main_kernel, cudaFuncAttributeMaxDynamicSharedMemorySize, smem_bytes);

    dim3 grid(VOCAB / BN, NBL / BM);   // (250, 4)
    main_kernel<<<grid, NTHREADS, smem_bytes>>>(out, b);
    (void)in_sizes; (void)n_in; (void)out_size;
}